// round 5
// baseline (speedup 1.0000x reference)
#include <cuda_runtime.h>
#include <cuda_bf16.h>

// Problem constants (fixed by the reference)
#define NN   100000
#define EE   3200000

// ---------------- scratch (device globals: no allocation allowed) ----------
// One buffer; kernels index it with compile-time offsets (in floats).
#define NS       ((size_t)51200000)       // NN*512
#define A_OFF    ((size_t)0)              // P1 concat  / layer2 pong
#define B_OFF    (NS)                     // GEMM acc / pre-norm H
#define C_OFF    (2*NS)                   // normalized h (ping) / H2
#define U_OFF    (3*NS)                   // NN*64
#define T1_OFF   (U_OFF + 6400000)        // NN*16
#define T2_OFF   (T1_OFF + 1600000)       // NN*16
#define W3T_OFF  (T2_OFF + 1600000)       // 512*64
#define BUF_TOTAL (W3T_OFF + 40000)

__device__ float g_buf[BUF_TOTAL];
__device__ float g_deg[NN];
__device__ float g_dinv[NN];
__device__ int   g_off[NN + 1];
__device__ int   g_cursor[NN];
__device__ int   g_src[EE];
__device__ float g_w[EE];
__device__ float g_stats[1024];
__device__ int   g_is64;

// ---------------- edge dtype detection ----------------
// int64 values < 100000 => every odd 32-bit word is 0.
// int32 random targets  => essentially all odd words nonzero over 8192 samples.
__global__ void k_detect(const int* __restrict__ ei32) {
    __shared__ int any;
    if (threadIdx.x == 0) any = 0;
    __syncthreads();
    for (int i = threadIdx.x; i < 8192; i += blockDim.x)
        if (ei32[2 * i + 1] != 0) any = 1;
    __syncthreads();
    if (threadIdx.x == 0) g_is64 = (any == 0) ? 1 : 0;
}

__device__ __forceinline__ int edge_val(const void* ei, size_t idx) {
    if (g_is64) return (int)((const long long*)ei)[idx];
    return ((const int*)ei)[idx];
}

// ---------------- graph preprocessing ----------------
__global__ void k_zero_init() {
    int i = blockIdx.x * blockDim.x + threadIdx.x;
    if (i < NN) { g_deg[i] = 0.f; g_cursor[i] = 0; }
    if (i < 1024) g_stats[i] = 0.f;
}

__global__ void k_zero_stats() {
    int i = blockIdx.x * blockDim.x + threadIdx.x;
    if (i < 1024) g_stats[i] = 0.f;
}

__global__ void k_deg(const void* __restrict__ ei) {
    int e = blockIdx.x * blockDim.x + threadIdx.x;
    if (e >= EE) return;
    int c = edge_val(ei, (size_t)EE + e);
    atomicAdd(&g_deg[c], 1.f);
}

__global__ void k_dinv() {
    int i = blockIdx.x * blockDim.x + threadIdx.x;
    if (i >= NN) return;
    float d = g_deg[i];
    g_dinv[i] = d > 0.f ? rsqrtf(d) : 0.f;
}

// single-block chunked exclusive scan over degree counts -> CSR offsets
__global__ void k_scan() {
    __shared__ int sh[1024];
    __shared__ int carry_s;
    if (threadIdx.x == 0) carry_s = 0;
    __syncthreads();
    for (int base = 0; base < NN; base += 1024) {
        int i = base + (int)threadIdx.x;
        int v = (i < NN) ? (int)g_deg[i] : 0;
        sh[threadIdx.x] = v;
        __syncthreads();
        for (int d = 1; d < 1024; d <<= 1) {
            int t = (threadIdx.x >= (unsigned)d) ? sh[threadIdx.x - d] : 0;
            __syncthreads();
            sh[threadIdx.x] += t;
            __syncthreads();
        }
        if (i < NN) g_off[i] = carry_s + sh[threadIdx.x] - v;  // exclusive
        __syncthreads();
        if (threadIdx.x == 0) carry_s += sh[1023];
        __syncthreads();
    }
    if (threadIdx.x == 0) g_off[NN] = carry_s;
}

__global__ void k_scatter(const void* __restrict__ ei) {
    int e = blockIdx.x * blockDim.x + threadIdx.x;
    if (e >= EE) return;
    int r = edge_val(ei, (size_t)e);
    int c = edge_val(ei, (size_t)EE + e);
    int pos = g_off[c] + atomicAdd(&g_cursor[c], 1);
    g_src[pos] = r;
    g_w[pos] = g_dinv[r] * g_dinv[c];
}

__global__ void k_copy_x(const float* __restrict__ x) {
    int idx = blockIdx.x * blockDim.x + threadIdx.x;  // over NN*32 float4
    if (idx >= NN * 32) return;
    int i = idx >> 5, c = idx & 31;
    ((float4*)(g_buf + A_OFF))[(size_t)i * 128 + c] = ((const float4*)x)[idx];
}

// ---------------- CSR gather propagation ----------------
// G threads per node; width = 4*G floats. out[i] = sum_e w_e * in[src_e] (+add)(+bias)
template <int G>
__global__ void k_prop(size_t in_off, int in_s4,
                       size_t out_off, int out_s4, float* out_ext,
                       size_t add_off, int add_s4, int has_add,
                       const float* __restrict__ bias) {
    const int per = 256 / G;
    int node = blockIdx.x * per + (int)(threadIdx.x / G);
    int lane = threadIdx.x % G;
    if (node >= NN) return;
    int s = g_off[node], e = g_off[node + 1];
    const float4* in4 = (const float4*)(g_buf + in_off);
    float4 acc = make_float4(0.f, 0.f, 0.f, 0.f);
    for (int p = s; p < e; ++p) {
        int   j  = __ldg(&g_src[p]);
        float wt = __ldg(&g_w[p]);
        float4 v = __ldg(&in4[(size_t)j * in_s4 + lane]);
        acc.x += wt * v.x; acc.y += wt * v.y;
        acc.z += wt * v.z; acc.w += wt * v.w;
    }
    if (has_add) {
        float4 a = ((const float4*)(g_buf + add_off))[(size_t)node * add_s4 + lane];
        acc.x += a.x; acc.y += a.y; acc.z += a.z; acc.w += a.w;
    }
    if (bias) {
        float4 b = ((const float4*)bias)[lane];
        acc.x += b.x; acc.y += b.y; acc.z += b.z; acc.w += b.w;
    }
    float4* out4 = out_ext ? (float4*)out_ext : (float4*)(g_buf + out_off);
    out4[(size_t)node * out_s4 + lane] = acc;
}

// ---------------- SGEMM 128x128x8, 256 threads, 8x8/thread ----------------
#define BM 128
#define BN 128
#define BK 8
#define TM 8
#define TN 8

__global__ __launch_bounds__(256) void k_sgemm(
    size_t a_off, const float* __restrict__ Bext, size_t b_off,
    size_t c_off, int M, int N, int K,
    const float* __restrict__ bias, int do_relu, int accum) {
    const float* A = g_buf + a_off;
    const float* B = Bext ? Bext : (g_buf + b_off);
    float* C = g_buf + c_off;
    __shared__ float As[BK][BM];
    __shared__ float Bs[BK][BN];
    int tid = threadIdx.x;
    int rowBase = blockIdx.y * BM;
    int colBase = blockIdx.x * BN;

    int aRow = tid >> 1;            // 0..127
    int aCol = (tid & 1) * 4;       // 0 / 4
    int bRow = tid >> 5;            // 0..7
    int bCol = (tid & 31) * 4;      // 0..124
    int tr = (tid >> 4) * TM;       // row in tile
    int tc = (tid & 15) * TN;       // col in tile

    float acc[TM][TN] = {};
    const float* Aptr = A + (size_t)(rowBase + aRow) * K + aCol;
    const float* Bptr = B + (size_t)bRow * N + colBase + bCol;
    bool aValid = (rowBase + aRow) < M;
    bool bValid = (colBase + bCol) < N;

    for (int k0 = 0; k0 < K; k0 += BK) {
        float4 av = aValid ? *(const float4*)Aptr : make_float4(0, 0, 0, 0);
        float4 bv = bValid ? *(const float4*)Bptr : make_float4(0, 0, 0, 0);
        Aptr += BK;
        Bptr += (size_t)BK * N;
        As[aCol + 0][aRow] = av.x;
        As[aCol + 1][aRow] = av.y;
        As[aCol + 2][aRow] = av.z;
        As[aCol + 3][aRow] = av.w;
        *(float4*)&Bs[bRow][bCol] = bv;
        __syncthreads();
#pragma unroll
        for (int kk = 0; kk < BK; ++kk) {
            float a[TM], b[TN];
#pragma unroll
            for (int i = 0; i < TM; ++i) a[i] = As[kk][tr + i];
#pragma unroll
            for (int j = 0; j < TN; ++j) b[j] = Bs[kk][tc + j];
#pragma unroll
            for (int i = 0; i < TM; ++i)
#pragma unroll
                for (int j = 0; j < TN; ++j) acc[i][j] += a[i] * b[j];
        }
        __syncthreads();
    }
#pragma unroll
    for (int i = 0; i < TM; ++i) {
        int r = rowBase + tr + i;
        if (r >= M) break;
#pragma unroll
        for (int j = 0; j < TN; ++j) {
            int c = colBase + tc + j;
            if (c >= N) continue;
            float v = acc[i][j];
            if (bias) v += bias[c];
            if (accum) v += C[(size_t)r * N + c];
            if (do_relu) v = fmaxf(v, 0.f);
            C[(size_t)r * N + c] = v;
        }
    }
}

// ---------------- GraphNorm (stats + normalize) ----------------
__global__ void k_stats(size_t x_off) {
    const float* x = g_buf + x_off;
    int col = threadIdx.x;  // blockDim = 512
    float s = 0.f, q = 0.f;
    for (int i = blockIdx.x; i < NN; i += gridDim.x) {
        float v = x[(size_t)i * 512 + col];
        s += v;
        q += v * v;
    }
    atomicAdd(&g_stats[col], s);
    atomicAdd(&g_stats[512 + col], q);
}

__global__ void k_gnorm(size_t x_off, size_t out_off,
                        const float* __restrict__ w,
                        const float* __restrict__ b,
                        const float* __restrict__ a) {
    const float* x = g_buf + x_off;
    float* out = g_buf + out_off;
    int col = threadIdx.x;  // 512
    const float invn = 1.f / (float)NN;
    float m  = g_stats[col] * invn;
    float aa = a[col];
    float am = aa * m;
    // var = E[(x-am)^2] = E[x^2] - 2*am*E[x] + (am)^2
    float var = g_stats[512 + col] * invn - 2.f * am * m + am * am;
    float sc = rsqrtf(var + 1e-5f) * w[col];
    float sh = b[col];
    for (int i = blockIdx.x; i < NN; i += gridDim.x)
        out[(size_t)i * 512 + col] = (x[(size_t)i * 512 + col] - am) * sc + sh;
}

// W3 (4,512,16) -> W3t (512, 64) with layout [i][k*16+j]
__global__ void k_w3t(const float* __restrict__ W3) {
    int idx = blockIdx.x * blockDim.x + threadIdx.x;
    if (idx >= 4 * 512 * 16) return;
    int k = idx >> 13;
    int r = idx & 8191;
    int i = r >> 4, j = r & 15;
    g_buf[W3T_OFF + i * 64 + k * 16 + j] = W3[idx];
}

// ---------------- launcher ----------------
extern "C" void kernel_launch(void* const* d_in, const int* in_sizes, int n_in,
                              void* d_out, int out_size) {
    const float* x    = (const float*)d_in[0];
    const void*  ei   = d_in[1];
    const float* W1   = (const float*)d_in[2];
    const float* b1   = (const float*)d_in[3];
    const float* W2   = (const float*)d_in[4];
    const float* b2   = (const float*)d_in[5];
    const float* W3   = (const float*)d_in[6];
    const float* b3   = (const float*)d_in[7];
    const float* gn1w = (const float*)d_in[8];
    const float* gn1b = (const float*)d_in[9];
    const float* gn1a = (const float*)d_in[10];
    const float* gn2w = (const float*)d_in[11];
    const float* gn2b = (const float*)d_in[12];
    const float* gn2a = (const float*)d_in[13];
    float* out = (float*)d_out;

    // graph preprocessing
    k_detect<<<1, 256>>>((const int*)ei);
    k_zero_init<<<(NN + 255) / 256, 256>>>();
    k_deg<<<(EE + 255) / 256, 256>>>(ei);
    k_dinv<<<(NN + 255) / 256, 256>>>();
    k_scan<<<1, 1024>>>();
    k_scatter<<<(EE + 255) / 256, 256>>>(ei);

    // ---- layer 1: props at width 128 into concat [x|Ax|A2x|A3x], one GEMM K=512
    k_copy_x<<<(NN * 32 + 255) / 256, 256>>>(x);
    k_prop<32><<<(NN + 7) / 8, 256>>>(A_OFF,       128, A_OFF + 128, 128, nullptr, 0, 0, 0, nullptr);
    k_prop<32><<<(NN + 7) / 8, 256>>>(A_OFF + 128, 128, A_OFF + 256, 128, nullptr, 0, 0, 0, nullptr);
    k_prop<32><<<(NN + 7) / 8, 256>>>(A_OFF + 256, 128, A_OFF + 384, 128, nullptr, 0, 0, 0, nullptr);
    dim3 g1(512 / BN, (NN + BM - 1) / BM);
    k_sgemm<<<g1, 256>>>(A_OFF, W1, 0, B_OFF, NN, 512, 512, b1, 1, 0);

    // graphnorm 1: B (pre-norm) -> C (h0)
    k_stats<<<512, 512>>>(B_OFF);
    k_gnorm<<<512, 512>>>(B_OFF, C_OFF, gn1w, gn1b, gn1a);

    // ---- layer 2: ping-pong props + accumulating GEMMs ----
    // ACC(B) = h0@W2[0] + b2
    k_sgemm<<<g1, 256>>>(C_OFF, W2,            0, B_OFF, NN, 512, 512, b2, 0, 0);
    // h1 = A*h0 (C->A); ACC += h1@W2[1]
    k_prop<128><<<(NN + 1) / 2, 256>>>(C_OFF, 128, A_OFF, 128, nullptr, 0, 0, 0, nullptr);
    k_sgemm<<<g1, 256>>>(A_OFF, W2 +  512*512, 0, B_OFF, NN, 512, 512, nullptr, 0, 1);
    // h2 = A*h1 (A->C); ACC += h2@W2[2]
    k_prop<128><<<(NN + 1) / 2, 256>>>(A_OFF, 128, C_OFF, 128, nullptr, 0, 0, 0, nullptr);
    k_sgemm<<<g1, 256>>>(C_OFF, W2 + 2*512*512, 0, B_OFF, NN, 512, 512, nullptr, 0, 1);
    // h3 = A*h2 (C->A); ACC += h3@W2[3], relu
    k_prop<128><<<(NN + 1) / 2, 256>>>(C_OFF, 128, A_OFF, 128, nullptr, 0, 0, 0, nullptr);
    k_sgemm<<<g1, 256>>>(A_OFF, W2 + 3*512*512, 0, B_OFF, NN, 512, 512, nullptr, 1, 1);

    // graphnorm 2: B -> C (H2)
    k_zero_stats<<<4, 256>>>();
    k_stats<<<512, 512>>>(B_OFF);
    k_gnorm<<<512, 512>>>(B_OFF, C_OFF, gn2w, gn2b, gn2a);

    // ---- layer 3: Horner on 16-wide features ----
    k_w3t<<<(4 * 512 * 16 + 255) / 256, 256>>>(W3);
    dim3 g3(1, (NN + BM - 1) / BM);
    k_sgemm<<<g3, 256>>>(C_OFF, nullptr, W3T_OFF, U_OFF, NN, 64, 512, nullptr, 0, 0);
    // t1 = A*u3 + u2 ; t2 = A*t1 + u1 ; out = A*t2 + u0 + b3
    k_prop<4><<<(NN + 63) / 64, 256>>>(U_OFF + 48, 16, T1_OFF, 4, nullptr, U_OFF + 32, 16, 1, nullptr);
    k_prop<4><<<(NN + 63) / 64, 256>>>(T1_OFF,      4, T2_OFF, 4, nullptr, U_OFF + 16, 16, 1, nullptr);
    k_prop<4><<<(NN + 63) / 64, 256>>>(T2_OFF,      4, 0,      4, out,     U_OFF,      16, 1, b3);
}

// round 9
// speedup vs baseline: 1.3554x; 1.3554x over previous
#include <cuda_runtime.h>
#include <cuda_bf16.h>
#include <cstdint>

// Problem constants (fixed by the reference)
#define NN   100000
#define EE   3200000

// ---------------- scratch (device globals: no allocation allowed) ----------
#define NS       ((size_t)51200000)       // NN*512 floats
#define A_OFF    ((size_t)0)              // fp32 ping (layer1 width128 / layer2 h1,h3)
#define B_OFF    (NS)                     // fp32 GEMM ACC / pre-norm H
#define C_OFF    (2*NS)                   // fp32 h0,h2 / H2
#define U_OFF    (3*NS)                   // NN*64
#define T1_OFF   (U_OFF + 6400000)        // NN*16
#define T2_OFF   (T1_OFF + 1600000)       // NN*16
#define W3T_OFF  (T2_OFF + 1600000)       // 512*64
#define BUF_TOTAL (W3T_OFF + 40000)

__device__ float g_buf[BUF_TOTAL];
__device__ float g_deg[NN];
__device__ float g_dinv[NN];
__device__ int   g_off[NN + 1];
__device__ int   g_cursor[NN];
__device__ int   g_src[EE];
__device__ float g_w[EE];
__device__ float g_stats[1024];
__device__ int   g_is64;

// bf16 split buffers: A operand hi/lo [NN,512], weights hi/lo [5][2][512*512]
__device__ __nv_bfloat16 g_ah[(size_t)NN * 512];
__device__ __nv_bfloat16 g_al[(size_t)NN * 512];
__device__ __nv_bfloat16 g_wb[5 * 2 * 262144];

// ---------------- PTX helpers (baseline ISA only — no 'a' features) --------
__device__ __forceinline__ uint32_t smem_u32(const void* p) {
    uint32_t a;
    asm("{ .reg .u64 t; cvta.to.shared.u64 t, %1; cvt.u32.u64 %0, t; }"
        : "=r"(a) : "l"(p));
    return a;
}

#define SWZ(off) ((off) ^ (((off) >> 3) & 0x70))

#define LDSM4(r, addr) \
    asm volatile("ldmatrix.sync.aligned.m8n8.x4.shared.b16 {%0,%1,%2,%3}, [%4];" \
        : "=r"((r)[0]), "=r"((r)[1]), "=r"((r)[2]), "=r"((r)[3]) : "r"(addr))
#define LDSM2(r, addr) \
    asm volatile("ldmatrix.sync.aligned.m8n8.x2.shared.b16 {%0,%1}, [%2];" \
        : "=r"((r)[0]), "=r"((r)[1]) : "r"(addr))
#define MMA_BF16(d, a, b) \
    asm volatile("mma.sync.aligned.m16n8k16.row.col.f32.bf16.bf16.f32 " \
        "{%0,%1,%2,%3}, {%4,%5,%6,%7}, {%8,%9}, {%0,%1,%2,%3};" \
        : "+f"((d)[0]), "+f"((d)[1]), "+f"((d)[2]), "+f"((d)[3]) \
        : "r"((a)[0]), "r"((a)[1]), "r"((a)[2]), "r"((a)[3]), \
          "r"((b)[0]), "r"((b)[1]))

// ---------------- bf16 split helpers ----------------
__device__ __forceinline__ void split1(float v, __nv_bfloat16& h, __nv_bfloat16& l) {
    h = __float2bfloat16(v);
    l = __float2bfloat16(v - __bfloat162float(h));
}
__device__ __forceinline__ void split4_store(float4 v, __nv_bfloat16* ph, __nv_bfloat16* pl) {
    union { __nv_bfloat16 b[4]; uint2 u; } H, L;
    split1(v.x, H.b[0], L.b[0]);
    split1(v.y, H.b[1], L.b[1]);
    split1(v.z, H.b[2], L.b[2]);
    split1(v.w, H.b[3], L.b[3]);
    *(uint2*)ph = H.u;
    *(uint2*)pl = L.u;
}

// ---------------- edge dtype detection ----------------
__global__ void k_detect(const int* __restrict__ ei32) {
    __shared__ int any;
    if (threadIdx.x == 0) any = 0;
    __syncthreads();
    for (int i = threadIdx.x; i < 8192; i += blockDim.x)
        if (ei32[2 * i + 1] != 0) any = 1;
    __syncthreads();
    if (threadIdx.x == 0) g_is64 = (any == 0) ? 1 : 0;
}
__device__ __forceinline__ int edge_val(const void* ei, size_t idx) {
    if (g_is64) return (int)((const long long*)ei)[idx];
    return ((const int*)ei)[idx];
}

// ---------------- graph preprocessing ----------------
__global__ void k_zero_init() {
    int i = blockIdx.x * blockDim.x + threadIdx.x;
    if (i < NN) { g_deg[i] = 0.f; g_cursor[i] = 0; }
    if (i < 1024) g_stats[i] = 0.f;
}
__global__ void k_zero_stats() {
    int i = blockIdx.x * blockDim.x + threadIdx.x;
    if (i < 1024) g_stats[i] = 0.f;
}
__global__ void k_deg(const void* __restrict__ ei) {
    int e = blockIdx.x * blockDim.x + threadIdx.x;
    if (e >= EE) return;
    atomicAdd(&g_deg[edge_val(ei, (size_t)EE + e)], 1.f);
}
__global__ void k_dinv() {
    int i = blockIdx.x * blockDim.x + threadIdx.x;
    if (i >= NN) return;
    float d = g_deg[i];
    g_dinv[i] = d > 0.f ? rsqrtf(d) : 0.f;
}
__global__ void k_scan() {
    __shared__ int sh[1024];
    __shared__ int carry_s;
    if (threadIdx.x == 0) carry_s = 0;
    __syncthreads();
    for (int base = 0; base < NN; base += 1024) {
        int i = base + (int)threadIdx.x;
        int v = (i < NN) ? (int)g_deg[i] : 0;
        sh[threadIdx.x] = v;
        __syncthreads();
        for (int d = 1; d < 1024; d <<= 1) {
            int t = (threadIdx.x >= (unsigned)d) ? sh[threadIdx.x - d] : 0;
            __syncthreads();
            sh[threadIdx.x] += t;
            __syncthreads();
        }
        if (i < NN) g_off[i] = carry_s + sh[threadIdx.x] - v;
        __syncthreads();
        if (threadIdx.x == 0) carry_s += sh[1023];
        __syncthreads();
    }
    if (threadIdx.x == 0) g_off[NN] = carry_s;
}
__global__ void k_scatter(const void* __restrict__ ei) {
    int e = blockIdx.x * blockDim.x + threadIdx.x;
    if (e >= EE) return;
    int r = edge_val(ei, (size_t)e);
    int c = edge_val(ei, (size_t)EE + e);
    int pos = g_off[c] + atomicAdd(&g_cursor[c], 1);
    g_src[pos] = r;
    g_w[pos] = g_dinv[r] * g_dinv[c];
}

// x (fp32 [NN,128]) -> bf16 hi/lo into cols 0..127 of g_ah/g_al
__global__ void k_xsplit(const float* __restrict__ x) {
    int idx = blockIdx.x * blockDim.x + threadIdx.x;
    if (idx >= NN * 32) return;
    int m = idx >> 5, c = (idx & 31) * 4;
    float4 v = ((const float4*)x)[idx];
    split4_store(v, &g_ah[(size_t)m * 512 + c], &g_al[(size_t)m * 512 + c]);
}

// weight transpose+split: W [512(K)][512(N)] fp32 -> g_wb[wsel] as [N][K] bf16 hi/lo
__global__ void k_wsplit(const float* __restrict__ W, int wsel) {
    int idx = blockIdx.x * blockDim.x + threadIdx.x;
    if (idx >= 262144) return;
    int n = idx >> 9, k = idx & 511;
    float v = W[(size_t)k * 512 + n];
    __nv_bfloat16 h, l;
    split1(v, h, l);
    g_wb[(size_t)wsel * 524288 + (size_t)n * 512 + k] = h;
    g_wb[(size_t)wsel * 524288 + 262144 + (size_t)n * 512 + k] = l;
}

// ---------------- CSR gather propagation (+ optional bf16 hi/lo emit) -------
template <int G>
__global__ void k_prop(const float* __restrict__ in_ext, size_t in_off, int in_s4,
                       size_t out_off, int out_s4, float* out_ext,
                       size_t add_off, int add_s4, int has_add,
                       const float* __restrict__ bias, int bcol) {
    const int per = 256 / G;
    int node = blockIdx.x * per + (int)(threadIdx.x / G);
    int lane = threadIdx.x % G;
    if (node >= NN) return;
    int s = g_off[node], e = g_off[node + 1];
    const float4* in4 = in_ext ? (const float4*)in_ext : (const float4*)(g_buf + in_off);
    float4 acc = make_float4(0.f, 0.f, 0.f, 0.f);
    for (int p = s; p < e; ++p) {
        int   j  = __ldg(&g_src[p]);
        float wt = __ldg(&g_w[p]);
        float4 v = __ldg(&in4[(size_t)j * in_s4 + lane]);
        acc.x += wt * v.x; acc.y += wt * v.y;
        acc.z += wt * v.z; acc.w += wt * v.w;
    }
    if (has_add) {
        float4 a = ((const float4*)(g_buf + add_off))[(size_t)node * add_s4 + lane];
        acc.x += a.x; acc.y += a.y; acc.z += a.z; acc.w += a.w;
    }
    if (bias) {
        float4 b = ((const float4*)bias)[lane];
        acc.x += b.x; acc.y += b.y; acc.z += b.z; acc.w += b.w;
    }
    float4* out4 = out_ext ? (float4*)out_ext : (float4*)(g_buf + out_off);
    out4[(size_t)node * out_s4 + lane] = acc;
    if (bcol >= 0) {
        size_t bo = (size_t)node * 512 + bcol + lane * 4;
        split4_store(acc, &g_ah[bo], &g_al[bo]);
    }
}

// ---------------- bf16x3 mma.sync GEMM: C[M,512], tile 128x128, K=512 -------
// A operand read directly from g_ah/g_al (device globals). B from g_wb[wsel].
// SMEM: 4 matrices of 128 rows x 64 bf16 (128B rows, SW128 swizzle), 16KB each
#define SA_H 0
#define SA_L 16384
#define SB_H 32768
#define SB_L 49152
#define GSM_TOTAL 65536

__global__ __launch_bounds__(256, 2)
void k_gemm_mma(int wsel, size_t c_off, int M,
                const float* __restrict__ bias, int relu, int accum) {
    extern __shared__ char smem[];
    uint32_t sb = smem_u32(smem);
    int tid = threadIdx.x, wid = tid >> 5, lane = tid & 31;
    int rowBase = blockIdx.y * 128, colBase = blockIdx.x * 128;
    int warpM = (wid & 1) * 64, warpN = (wid >> 1) * 32;
    const __nv_bfloat16* Ahi = g_ah;
    const __nv_bfloat16* Alo = g_al;
    const __nv_bfloat16* Bhi = g_wb + (size_t)wsel * 524288;
    const __nv_bfloat16* Blo = Bhi + 262144;

    float acc[4][4][4];
#pragma unroll
    for (int mi = 0; mi < 4; ++mi)
#pragma unroll
        for (int ni = 0; ni < 4; ++ni)
#pragma unroll
            for (int q = 0; q < 4; ++q) acc[mi][ni][q] = 0.f;

    for (int c = 0; c < 8; ++c) {
        // stage K-chunk c (cols c*64 .. c*64+63) for all 4 operand matrices
#pragma unroll
        for (int i = 0; i < 4; ++i) {
            int it = tid + i * 256;           // 0..1023
            int r = it >> 3, u = it & 7;      // row, 16B unit
            uint32_t so = SWZ((uint32_t)(r * 128 + u * 16));
            int ar = rowBase + r;
            uint4 vh = make_uint4(0, 0, 0, 0), vl = vh;
            if (ar < M) {
                vh = ((const uint4*)(Ahi + (size_t)ar * 512 + c * 64))[u];
                vl = ((const uint4*)(Alo + (size_t)ar * 512 + c * 64))[u];
            }
            *(uint4*)(smem + SA_H + so) = vh;
            *(uint4*)(smem + SA_L + so) = vl;
            int br = colBase + r;
            *(uint4*)(smem + SB_H + so) = ((const uint4*)(Bhi + (size_t)br * 512 + c * 64))[u];
            *(uint4*)(smem + SB_L + so) = ((const uint4*)(Blo + (size_t)br * 512 + c * 64))[u];
        }
        __syncthreads();
#pragma unroll
        for (int ks = 0; ks < 4; ++ks) {
            // B fragments (k16 x n8), storage is [n][k] = col-major k x n
            uint32_t bH[4][2], bL[4][2];
            int bl = lane & 15;
            int brow = warpN + (bl & 7);
            uint32_t bunit = ks * 2 + ((bl >> 3) & 1);
#pragma unroll
            for (int ni = 0; ni < 4; ++ni) {
                uint32_t off = SWZ((uint32_t)((brow + ni * 8) * 128 + bunit * 16));
                LDSM2(bH[ni], sb + SB_H + off);
                LDSM2(bL[ni], sb + SB_L + off);
            }
            int arow = warpM + (lane & 15);
            uint32_t aunit = ks * 2 + (lane >> 4);
#pragma unroll
            for (int mi = 0; mi < 4; ++mi) {
                uint32_t aH[4], aL[4];
                uint32_t off = SWZ((uint32_t)((arow + mi * 16) * 128 + aunit * 16));
                LDSM4(aH, sb + SA_H + off);
                LDSM4(aL, sb + SA_L + off);
#pragma unroll
                for (int ni = 0; ni < 4; ++ni) {
                    MMA_BF16(acc[mi][ni], aH, bH[ni]);
                    MMA_BF16(acc[mi][ni], aH, bL[ni]);
                    MMA_BF16(acc[mi][ni], aL, bH[ni]);
                }
            }
        }
        __syncthreads();
    }

    // epilogue: c frag thread t -> rows (t>>2), (t>>2)+8; cols 2*(t&3), +1
    float* C = g_buf + c_off;
#pragma unroll
    for (int mi = 0; mi < 4; ++mi) {
        int r0 = rowBase + warpM + mi * 16 + (lane >> 2);
#pragma unroll
        for (int ni = 0; ni < 4; ++ni) {
            int cc = colBase + warpN + ni * 8 + (lane & 3) * 2;
            float2 v0 = make_float2(acc[mi][ni][0], acc[mi][ni][1]);
            float2 v1 = make_float2(acc[mi][ni][2], acc[mi][ni][3]);
            if (bias) {
                float2 bb = *(const float2*)&bias[cc];
                v0.x += bb.x; v0.y += bb.y;
                v1.x += bb.x; v1.y += bb.y;
            }
            if (r0 < M) {
                float* p = C + (size_t)r0 * 512 + cc;
                if (accum) { float2 o = *(float2*)p; v0.x += o.x; v0.y += o.y; }
                if (relu) { v0.x = fmaxf(v0.x, 0.f); v0.y = fmaxf(v0.y, 0.f); }
                *(float2*)p = v0;
            }
            if (r0 + 8 < M) {
                float* p = C + (size_t)(r0 + 8) * 512 + cc;
                if (accum) { float2 o = *(float2*)p; v1.x += o.x; v1.y += o.y; }
                if (relu) { v1.x = fmaxf(v1.x, 0.f); v1.y = fmaxf(v1.y, 0.f); }
                *(float2*)p = v1;
            }
        }
    }
}

// ---------------- SIMT SGEMM (layer 3 only, N=64) ----------------
#define BM 128
#define BN 128
#define BK 8
#define TM 8
#define TN 8
__global__ __launch_bounds__(256) void k_sgemm(
    size_t a_off, size_t b_off, size_t c_off, int M, int N, int K) {
    const float* A = g_buf + a_off;
    const float* B = g_buf + b_off;
    float* C = g_buf + c_off;
    __shared__ float As[BK][BM];
    __shared__ float Bs[BK][BN];
    int tid = threadIdx.x;
    int rowBase = blockIdx.y * BM;
    int colBase = blockIdx.x * BN;
    int aRow = tid >> 1, aCol = (tid & 1) * 4;
    int bRow = tid >> 5, bCol = (tid & 31) * 4;
    int tr = (tid >> 4) * TM, tc = (tid & 15) * TN;
    float acc[TM][TN] = {};
    const float* Aptr = A + (size_t)(rowBase + aRow) * K + aCol;
    const float* Bptr = B + (size_t)bRow * N + colBase + bCol;
    bool aValid = (rowBase + aRow) < M;
    bool bValid = (colBase + bCol) < N;
    for (int k0 = 0; k0 < K; k0 += BK) {
        float4 av = aValid ? *(const float4*)Aptr : make_float4(0, 0, 0, 0);
        float4 bv = bValid ? *(const float4*)Bptr : make_float4(0, 0, 0, 0);
        Aptr += BK;
        Bptr += (size_t)BK * N;
        As[aCol + 0][aRow] = av.x;
        As[aCol + 1][aRow] = av.y;
        As[aCol + 2][aRow] = av.z;
        As[aCol + 3][aRow] = av.w;
        *(float4*)&Bs[bRow][bCol] = bv;
        __syncthreads();
#pragma unroll
        for (int kk = 0; kk < BK; ++kk) {
            float a[TM], b[TN];
#pragma unroll
            for (int i = 0; i < TM; ++i) a[i] = As[kk][tr + i];
#pragma unroll
            for (int j = 0; j < TN; ++j) b[j] = Bs[kk][tc + j];
#pragma unroll
            for (int i = 0; i < TM; ++i)
#pragma unroll
                for (int j = 0; j < TN; ++j) acc[i][j] += a[i] * b[j];
        }
        __syncthreads();
    }
#pragma unroll
    for (int i = 0; i < TM; ++i) {
        int r = rowBase + tr + i;
        if (r >= M) break;
#pragma unroll
        for (int j = 0; j < TN; ++j) {
            int c = colBase + tc + j;
            if (c >= N) continue;
            C[(size_t)r * N + c] = acc[i][j];
        }
    }
}

// ---------------- GraphNorm ----------------
__global__ void k_stats(size_t x_off) {
    const float* x = g_buf + x_off;
    int col = threadIdx.x;
    float s = 0.f, q = 0.f;
    for (int i = blockIdx.x; i < NN; i += gridDim.x) {
        float v = x[(size_t)i * 512 + col];
        s += v;
        q += v * v;
    }
    atomicAdd(&g_stats[col], s);
    atomicAdd(&g_stats[512 + col], q);
}
__global__ void k_gnorm(size_t x_off, size_t out_off,
                        const float* __restrict__ w,
                        const float* __restrict__ b,
                        const float* __restrict__ a, int emit_bf16) {
    const float* x = g_buf + x_off;
    float* out = g_buf + out_off;
    int col = threadIdx.x;
    const float invn = 1.f / (float)NN;
    float m  = g_stats[col] * invn;
    float am = a[col] * m;
    float var = g_stats[512 + col] * invn - 2.f * am * m + am * am;
    float sc = rsqrtf(var + 1e-5f) * w[col];
    float sh = b[col];
    for (int i = blockIdx.x; i < NN; i += gridDim.x) {
        float v = (x[(size_t)i * 512 + col] - am) * sc + sh;
        out[(size_t)i * 512 + col] = v;
        if (emit_bf16) {
            __nv_bfloat16 h, l;
            split1(v, h, l);
            g_ah[(size_t)i * 512 + col] = h;
            g_al[(size_t)i * 512 + col] = l;
        }
    }
}

// W3 (4,512,16) -> W3t (512,64): [i][k*16+j]
__global__ void k_w3t(const float* __restrict__ W3) {
    int idx = blockIdx.x * blockDim.x + threadIdx.x;
    if (idx >= 4 * 512 * 16) return;
    int k = idx >> 13;
    int r = idx & 8191;
    int i = r >> 4, j = r & 15;
    g_buf[W3T_OFF + i * 64 + k * 16 + j] = W3[idx];
}

// ---------------- launcher ----------------
extern "C" void kernel_launch(void* const* d_in, const int* in_sizes, int n_in,
                              void* d_out, int out_size) {
    const float* x    = (const float*)d_in[0];
    const void*  ei   = d_in[1];
    const float* W1   = (const float*)d_in[2];
    const float* b1   = (const float*)d_in[3];
    const float* W2   = (const float*)d_in[4];
    const float* b2   = (const float*)d_in[5];
    const float* W3   = (const float*)d_in[6];
    const float* b3   = (const float*)d_in[7];
    const float* gn1w = (const float*)d_in[8];
    const float* gn1b = (const float*)d_in[9];
    const float* gn1a = (const float*)d_in[10];
    const float* gn2w = (const float*)d_in[11];
    const float* gn2b = (const float*)d_in[12];
    const float* gn2a = (const float*)d_in[13];
    float* out = (float*)d_out;

    cudaFuncSetAttribute(k_gemm_mma, cudaFuncAttributeMaxDynamicSharedMemorySize, GSM_TOTAL);

    // graph preprocessing
    k_detect<<<1, 256>>>((const int*)ei);
    k_zero_init<<<(NN + 255) / 256, 256>>>();
    k_deg<<<(EE + 255) / 256, 256>>>(ei);
    k_dinv<<<(NN + 255) / 256, 256>>>();
    k_scan<<<1, 1024>>>();
    k_scatter<<<(EE + 255) / 256, 256>>>(ei);

    // weight splits (independent of graph)
    k_wsplit<<<1024, 256>>>(W1, 0);
    k_wsplit<<<1024, 256>>>(W2, 1);
    k_wsplit<<<1024, 256>>>(W2 + 262144, 2);
    k_wsplit<<<1024, 256>>>(W2 + 524288, 3);
    k_wsplit<<<1024, 256>>>(W2 + 786432, 4);

    const size_t P0 = A_OFF;                       // [NN,128] fp32 ping
    const size_t P1 = A_OFF + (size_t)NN * 128;    // [NN,128] fp32 pong
    dim3 gg(4, (NN + 127) / 128);

    // ---- layer 1: width-128 props; bf16 concat cols fill g_ah/g_al ----
    k_xsplit<<<(NN * 32 + 255) / 256, 256>>>(x);
    k_prop<32><<<(NN + 7) / 8, 256>>>(x, 0, 32, P0, 32, nullptr, 0, 0, 0, nullptr, 128);
    k_prop<32><<<(NN + 7) / 8, 256>>>(nullptr, P0, 32, P1, 32, nullptr, 0, 0, 0, nullptr, 256);
    k_prop<32><<<(NN + 7) / 8, 256>>>(nullptr, P1, 32, P0, 32, nullptr, 0, 0, 0, nullptr, 384);
    k_gemm_mma<<<gg, 256, GSM_TOTAL>>>(0, B_OFF, NN, b1, 1, 0);

    // graphnorm 1: B -> C fp32 h0 (+bf16)
    k_stats<<<512, 512>>>(B_OFF);
    k_gnorm<<<512, 512>>>(B_OFF, C_OFF, gn1w, gn1b, gn1a, 1);

    // ---- layer 2: ACC = sum_k h_k @ W2[k] ----
    k_gemm_mma<<<gg, 256, GSM_TOTAL>>>(1, B_OFF, NN, b2, 0, 0);
    k_prop<128><<<(NN + 1) / 2, 256>>>(nullptr, C_OFF, 128, A_OFF, 128, nullptr, 0, 0, 0, nullptr, 0);
    k_gemm_mma<<<gg, 256, GSM_TOTAL>>>(2, B_OFF, NN, nullptr, 0, 1);
    k_prop<128><<<(NN + 1) / 2, 256>>>(nullptr, A_OFF, 128, C_OFF, 128, nullptr, 0, 0, 0, nullptr, 0);
    k_gemm_mma<<<gg, 256, GSM_TOTAL>>>(3, B_OFF, NN, nullptr, 0, 1);
    k_prop<128><<<(NN + 1) / 2, 256>>>(nullptr, C_OFF, 128, A_OFF, 128, nullptr, 0, 0, 0, nullptr, 0);
    k_gemm_mma<<<gg, 256, GSM_TOTAL>>>(4, B_OFF, NN, nullptr, 1, 1);

    // graphnorm 2: B -> C (H2, fp32 only)
    k_zero_stats<<<4, 256>>>();
    k_stats<<<512, 512>>>(B_OFF);
    k_gnorm<<<512, 512>>>(B_OFF, C_OFF, gn2w, gn2b, gn2a, 0);

    // ---- layer 3: Horner on 16-wide features (SIMT) ----
    k_w3t<<<(4 * 512 * 16 + 255) / 256, 256>>>(W3);
    dim3 g3(1, (NN + BM - 1) / BM);
    k_sgemm<<<g3, 256>>>(C_OFF, W3T_OFF, U_OFF, NN, 64, 512);
    k_prop<4><<<(NN + 63) / 64, 256>>>(nullptr, U_OFF + 48, 16, T1_OFF, 4, nullptr, U_OFF + 32, 16, 1, nullptr, -1);
    k_prop<4><<<(NN + 63) / 64, 256>>>(nullptr, T1_OFF, 4, T2_OFF, 4, nullptr, U_OFF + 16, 16, 1, nullptr, -1);
    k_prop<4><<<(NN + 63) / 64, 256>>>(nullptr, T2_OFF, 4, 0, 4, out, U_OFF, 16, 1, b3, -1);
}

// round 10
// speedup vs baseline: 1.8828x; 1.3892x over previous
#include <cuda_runtime.h>
#include <cuda_bf16.h>
#include <cstdint>

// Problem constants (fixed by the reference)
#define NN   100000
#define EE   3200000

// ---------------- scratch (device globals: no allocation allowed) ----------
#define NS       ((size_t)51200000)       // NN*512 floats
#define A_OFF    ((size_t)0)              // fp32 ping (layer1 width128 / layer2 h1,h3)
#define B_OFF    (NS)                     // fp32 GEMM ACC / pre-norm H
#define C_OFF    (2*NS)                   // fp32 h0,h2 / H2
#define U_OFF    (3*NS)                   // NN*64
#define T1_OFF   (U_OFF + 6400000)        // NN*16
#define T2_OFF   (T1_OFF + 1600000)       // NN*16
#define W3T_OFF  (T2_OFF + 1600000)       // 512*64
#define BUF_TOTAL (W3T_OFF + 40000)

__device__ float g_buf[BUF_TOTAL];
__device__ float g_deg[NN];
__device__ float g_dinv[NN];
__device__ int   g_off[NN + 1];
__device__ int   g_cursor[NN];
__device__ int   g_src[EE];
__device__ float g_w[EE];
__device__ float g_stats[1024];
__device__ int   g_is64;

// bf16 split buffers: A operand hi/lo [NN,512], weights hi/lo [5][2][512*512]
__device__ __nv_bfloat16 g_ah[(size_t)NN * 512];
__device__ __nv_bfloat16 g_al[(size_t)NN * 512];
__device__ __nv_bfloat16 g_wb[5 * 2 * 262144];

// ---------------- PTX helpers (baseline ISA only — no 'a' features) --------
__device__ __forceinline__ uint32_t smem_u32(const void* p) {
    uint32_t a;
    asm("{ .reg .u64 t; cvta.to.shared.u64 t, %1; cvt.u32.u64 %0, t; }"
        : "=r"(a) : "l"(p));
    return a;
}

#define SWZ(off)   ((off) ^ (((off) >> 3) & 0x70))
#define SWZ64(off) ((off) ^ (((off) >> 3) & 0x30))

#define LDSM4(r, addr) \
    asm volatile("ldmatrix.sync.aligned.m8n8.x4.shared.b16 {%0,%1,%2,%3}, [%4];" \
        : "=r"((r)[0]), "=r"((r)[1]), "=r"((r)[2]), "=r"((r)[3]) : "r"(addr))
#define LDSM2(r, addr) \
    asm volatile("ldmatrix.sync.aligned.m8n8.x2.shared.b16 {%0,%1}, [%2];" \
        : "=r"((r)[0]), "=r"((r)[1]) : "r"(addr))
#define MMA_BF16(d, a, b) \
    asm volatile("mma.sync.aligned.m16n8k16.row.col.f32.bf16.bf16.f32 " \
        "{%0,%1,%2,%3}, {%4,%5,%6,%7}, {%8,%9}, {%0,%1,%2,%3};" \
        : "+f"((d)[0]), "+f"((d)[1]), "+f"((d)[2]), "+f"((d)[3]) \
        : "r"((a)[0]), "r"((a)[1]), "r"((a)[2]), "r"((a)[3]), \
          "r"((b)[0]), "r"((b)[1]))
#define CP_ASYNC16(smaddr, gptr, sz) \
    asm volatile("cp.async.cg.shared.global [%0], [%1], 16, %2;" \
        :: "r"(smaddr), "l"(gptr), "r"(sz) : "memory")

// ---------------- bf16 split helpers ----------------
__device__ __forceinline__ void split1(float v, __nv_bfloat16& h, __nv_bfloat16& l) {
    h = __float2bfloat16(v);
    l = __float2bfloat16(v - __bfloat162float(h));
}
__device__ __forceinline__ void split4_store(float4 v, __nv_bfloat16* ph, __nv_bfloat16* pl) {
    union { __nv_bfloat16 b[4]; uint2 u; } H, L;
    split1(v.x, H.b[0], L.b[0]);
    split1(v.y, H.b[1], L.b[1]);
    split1(v.z, H.b[2], L.b[2]);
    split1(v.w, H.b[3], L.b[3]);
    *(uint2*)ph = H.u;
    *(uint2*)pl = L.u;
}

// ---------------- edge dtype detection ----------------
__global__ void k_detect(const int* __restrict__ ei32) {
    __shared__ int any;
    if (threadIdx.x == 0) any = 0;
    __syncthreads();
    for (int i = threadIdx.x; i < 8192; i += blockDim.x)
        if (ei32[2 * i + 1] != 0) any = 1;
    __syncthreads();
    if (threadIdx.x == 0) g_is64 = (any == 0) ? 1 : 0;
}
__device__ __forceinline__ int edge_val(const void* ei, size_t idx) {
    if (g_is64) return (int)((const long long*)ei)[idx];
    return ((const int*)ei)[idx];
}

// ---------------- graph preprocessing ----------------
__global__ void k_zero_init() {
    int i = blockIdx.x * blockDim.x + threadIdx.x;
    if (i < NN) { g_deg[i] = 0.f; g_cursor[i] = 0; }
    if (i < 1024) g_stats[i] = 0.f;
}
__global__ void k_zero_stats() {
    int i = blockIdx.x * blockDim.x + threadIdx.x;
    if (i < 1024) g_stats[i] = 0.f;
}
__global__ void k_deg(const void* __restrict__ ei) {
    int e = blockIdx.x * blockDim.x + threadIdx.x;
    if (e >= EE) return;
    atomicAdd(&g_deg[edge_val(ei, (size_t)EE + e)], 1.f);
}
__global__ void k_dinv() {
    int i = blockIdx.x * blockDim.x + threadIdx.x;
    if (i >= NN) return;
    float d = g_deg[i];
    g_dinv[i] = d > 0.f ? rsqrtf(d) : 0.f;
}
__global__ void k_scan() {
    __shared__ int sh[1024];
    __shared__ int carry_s;
    if (threadIdx.x == 0) carry_s = 0;
    __syncthreads();
    for (int base = 0; base < NN; base += 1024) {
        int i = base + (int)threadIdx.x;
        int v = (i < NN) ? (int)g_deg[i] : 0;
        sh[threadIdx.x] = v;
        __syncthreads();
        for (int d = 1; d < 1024; d <<= 1) {
            int t = (threadIdx.x >= (unsigned)d) ? sh[threadIdx.x - d] : 0;
            __syncthreads();
            sh[threadIdx.x] += t;
            __syncthreads();
        }
        if (i < NN) g_off[i] = carry_s + sh[threadIdx.x] - v;
        __syncthreads();
        if (threadIdx.x == 0) carry_s += sh[1023];
        __syncthreads();
    }
    if (threadIdx.x == 0) g_off[NN] = carry_s;
}
__global__ void k_scatter(const void* __restrict__ ei) {
    int e = blockIdx.x * blockDim.x + threadIdx.x;
    if (e >= EE) return;
    int r = edge_val(ei, (size_t)e);
    int c = edge_val(ei, (size_t)EE + e);
    int pos = g_off[c] + atomicAdd(&g_cursor[c], 1);
    g_src[pos] = r;
    g_w[pos] = g_dinv[r] * g_dinv[c];
}

// x (fp32 [NN,128]) -> bf16 hi/lo into cols 0..127 of g_ah/g_al
__global__ void k_xsplit(const float* __restrict__ x) {
    int idx = blockIdx.x * blockDim.x + threadIdx.x;
    if (idx >= NN * 32) return;
    int m = idx >> 5, c = (idx & 31) * 4;
    float4 v = ((const float4*)x)[idx];
    split4_store(v, &g_ah[(size_t)m * 512 + c], &g_al[(size_t)m * 512 + c]);
}

// weight transpose+split: W [512(K)][512(N)] fp32 -> g_wb[wsel] as [N][K] bf16 hi/lo
__global__ void k_wsplit(const float* __restrict__ W, int wsel) {
    int idx = blockIdx.x * blockDim.x + threadIdx.x;
    if (idx >= 262144) return;
    int n = idx >> 9, k = idx & 511;
    float v = W[(size_t)k * 512 + n];
    __nv_bfloat16 h, l;
    split1(v, h, l);
    g_wb[(size_t)wsel * 524288 + (size_t)n * 512 + k] = h;
    g_wb[(size_t)wsel * 524288 + 262144 + (size_t)n * 512 + k] = l;
}

// ---------------- CSR gather propagation (+ optional bf16 hi/lo emit) -------
// G threads/node, 4 cols per thread. cbase4 = column offset in float4 units.
template <int G>
__global__ void k_prop(const float* __restrict__ in_ext, size_t in_off, int in_s4,
                       size_t out_off, int out_s4, float* out_ext,
                       size_t add_off, int add_s4, int has_add,
                       const float* __restrict__ bias, int bcol, int cbase4) {
    const int per = 256 / G;
    int node = blockIdx.x * per + (int)(threadIdx.x / G);
    int lane = threadIdx.x % G;
    if (node >= NN) return;
    int s = g_off[node], e = g_off[node + 1];
    const float4* in4 = in_ext ? (const float4*)in_ext : (const float4*)(g_buf + in_off);
    float4 acc = make_float4(0.f, 0.f, 0.f, 0.f);
    int p = s;
    for (; p + 1 < e; p += 2) {
        int   j0 = __ldg(&g_src[p]),     j1 = __ldg(&g_src[p + 1]);
        float w0 = __ldg(&g_w[p]),       w1 = __ldg(&g_w[p + 1]);
        float4 v0 = __ldg(&in4[(size_t)j0 * in_s4 + cbase4 + lane]);
        float4 v1 = __ldg(&in4[(size_t)j1 * in_s4 + cbase4 + lane]);
        acc.x += w0 * v0.x + w1 * v1.x;
        acc.y += w0 * v0.y + w1 * v1.y;
        acc.z += w0 * v0.z + w1 * v1.z;
        acc.w += w0 * v0.w + w1 * v1.w;
    }
    if (p < e) {
        int   j  = __ldg(&g_src[p]);
        float wt = __ldg(&g_w[p]);
        float4 v = __ldg(&in4[(size_t)j * in_s4 + cbase4 + lane]);
        acc.x += wt * v.x; acc.y += wt * v.y;
        acc.z += wt * v.z; acc.w += wt * v.w;
    }
    if (has_add) {
        float4 a = ((const float4*)(g_buf + add_off))[(size_t)node * add_s4 + cbase4 + lane];
        acc.x += a.x; acc.y += a.y; acc.z += a.z; acc.w += a.w;
    }
    if (bias) {
        float4 b = ((const float4*)bias)[cbase4 + lane];
        acc.x += b.x; acc.y += b.y; acc.z += b.z; acc.w += b.w;
    }
    float4* out4 = out_ext ? (float4*)out_ext : (float4*)(g_buf + out_off);
    out4[(size_t)node * out_s4 + cbase4 + lane] = acc;
    if (bcol >= 0) {
        size_t bo = (size_t)node * 512 + bcol + lane * 4;
        split4_store(acc, &g_ah[bo], &g_al[bo]);
    }
}

// ---------------- bf16x3 mma.sync GEMM, cp.async 2-stage pipeline ----------
// C[M,512], CTA tile 128x128, K=512 in 16 chunks of 32.
// Stage = 4 matrices x (128 rows x 64B, SW64 swizzle) = 32KB; 2 stages = 64KB.
#define GSM_TOTAL 65536

__global__ __launch_bounds__(256, 2)
void k_gemm_mma(int wsel, size_t c_off, int M,
                const float* __restrict__ bias, int relu, int accum) {
    extern __shared__ char smem[];
    uint32_t sb = smem_u32(smem);
    int tid = threadIdx.x, wid = tid >> 5, lane = tid & 31;
    int rowBase = blockIdx.y * 128, colBase = blockIdx.x * 128;
    int warpM = (wid & 1) * 64, warpN = (wid >> 1) * 32;
    const __nv_bfloat16* Bhi = g_wb + (size_t)wsel * 524288;
    const __nv_bfloat16* Blo = Bhi + 262144;

    float acc[4][4][4];
#pragma unroll
    for (int mi = 0; mi < 4; ++mi)
#pragma unroll
        for (int ni = 0; ni < 4; ++ni)
#pragma unroll
            for (int q = 0; q < 4; ++q) acc[mi][ni][q] = 0.f;

    auto load_stage = [&](int c, int st) {
#pragma unroll
        for (int i = 0; i < 8; ++i) {
            int it = tid + i * 256;           // 0..2047
            int mat = it >> 9;                // 0 AH, 1 AL, 2 BH, 3 BL
            int idx = it & 511;
            int r = idx >> 2, u = idx & 3;    // row 0..127, 16B unit 0..3
            uint32_t so = sb + (uint32_t)st * 32768 + (uint32_t)mat * 8192 +
                          SWZ64((uint32_t)(r * 64 + u * 16));
            const __nv_bfloat16* src;
            int gr, sz = 16;
            if (mat == 0)      { src = g_ah; gr = rowBase + r; if (gr >= M) { gr = 0; sz = 0; } }
            else if (mat == 1) { src = g_al; gr = rowBase + r; if (gr >= M) { gr = 0; sz = 0; } }
            else if (mat == 2) { src = Bhi;  gr = colBase + r; }
            else               { src = Blo;  gr = colBase + r; }
            const void* gp = src + (size_t)gr * 512 + c * 32 + u * 8;
            CP_ASYNC16(so, gp, sz);
        }
        asm volatile("cp.async.commit_group;" ::: "memory");
    };

    load_stage(0, 0);
    for (int c = 0; c < 16; ++c) {
        if (c + 1 < 16) {
            load_stage(c + 1, (c + 1) & 1);
            asm volatile("cp.async.wait_group 1;" ::: "memory");
        } else {
            asm volatile("cp.async.wait_group 0;" ::: "memory");
        }
        __syncthreads();
        uint32_t sbase = sb + (uint32_t)(c & 1) * 32768;
#pragma unroll
        for (int ks = 0; ks < 2; ++ks) {
            uint32_t bH[4][2], bL[4][2];
            int bl = lane & 15;
            int brow0 = warpN + (bl & 7);
            uint32_t bunit = ks * 2 + ((bl >> 3) & 1);
#pragma unroll
            for (int ni = 0; ni < 4; ++ni) {
                uint32_t off = SWZ64((uint32_t)((brow0 + ni * 8) * 64 + bunit * 16));
                LDSM2(bH[ni], sbase + 16384 + off);
                LDSM2(bL[ni], sbase + 24576 + off);
            }
            int arow = warpM + (lane & 15);
            uint32_t aunit = ks * 2 + (lane >> 4);
#pragma unroll
            for (int mi = 0; mi < 4; ++mi) {
                uint32_t aH[4], aL[4];
                uint32_t off = SWZ64((uint32_t)((arow + mi * 16) * 64 + aunit * 16));
                LDSM4(aH, sbase + off);
                LDSM4(aL, sbase + 8192 + off);
#pragma unroll
                for (int ni = 0; ni < 4; ++ni) {
                    MMA_BF16(acc[mi][ni], aH, bH[ni]);
                    MMA_BF16(acc[mi][ni], aH, bL[ni]);
                    MMA_BF16(acc[mi][ni], aL, bH[ni]);
                }
            }
        }
        __syncthreads();
    }

    // epilogue: c frag thread t -> rows (t>>2), (t>>2)+8; cols 2*(t&3), +1
    float* C = g_buf + c_off;
#pragma unroll
    for (int mi = 0; mi < 4; ++mi) {
        int r0 = rowBase + warpM + mi * 16 + (lane >> 2);
#pragma unroll
        for (int ni = 0; ni < 4; ++ni) {
            int cc = colBase + warpN + ni * 8 + (lane & 3) * 2;
            float2 v0 = make_float2(acc[mi][ni][0], acc[mi][ni][1]);
            float2 v1 = make_float2(acc[mi][ni][2], acc[mi][ni][3]);
            if (bias) {
                float2 bb = *(const float2*)&bias[cc];
                v0.x += bb.x; v0.y += bb.y;
                v1.x += bb.x; v1.y += bb.y;
            }
            if (r0 < M) {
                float* p = C + (size_t)r0 * 512 + cc;
                if (accum) { float2 o = *(float2*)p; v0.x += o.x; v0.y += o.y; }
                if (relu) { v0.x = fmaxf(v0.x, 0.f); v0.y = fmaxf(v0.y, 0.f); }
                *(float2*)p = v0;
            }
            if (r0 + 8 < M) {
                float* p = C + (size_t)(r0 + 8) * 512 + cc;
                if (accum) { float2 o = *(float2*)p; v1.x += o.x; v1.y += o.y; }
                if (relu) { v1.x = fmaxf(v1.x, 0.f); v1.y = fmaxf(v1.y, 0.f); }
                *(float2*)p = v1;
            }
        }
    }
}

// ---------------- SIMT SGEMM (layer 3 only, N=64) ----------------
#define BM 128
#define BN 128
#define BK 8
#define TM 8
#define TN 8
__global__ __launch_bounds__(256) void k_sgemm(
    size_t a_off, size_t b_off, size_t c_off, int M, int N, int K) {
    const float* A = g_buf + a_off;
    const float* B = g_buf + b_off;
    float* C = g_buf + c_off;
    __shared__ float As[BK][BM];
    __shared__ float Bs[BK][BN];
    int tid = threadIdx.x;
    int rowBase = blockIdx.y * BM;
    int colBase = blockIdx.x * BN;
    int aRow = tid >> 1, aCol = (tid & 1) * 4;
    int bRow = tid >> 5, bCol = (tid & 31) * 4;
    int tr = (tid >> 4) * TM, tc = (tid & 15) * TN;
    float acc[TM][TN] = {};
    const float* Aptr = A + (size_t)(rowBase + aRow) * K + aCol;
    const float* Bptr = B + (size_t)bRow * N + colBase + bCol;
    bool aValid = (rowBase + aRow) < M;
    bool bValid = (colBase + bCol) < N;
    for (int k0 = 0; k0 < K; k0 += BK) {
        float4 av = aValid ? *(const float4*)Aptr : make_float4(0, 0, 0, 0);
        float4 bv = bValid ? *(const float4*)Bptr : make_float4(0, 0, 0, 0);
        Aptr += BK;
        Bptr += (size_t)BK * N;
        As[aCol + 0][aRow] = av.x;
        As[aCol + 1][aRow] = av.y;
        As[aCol + 2][aRow] = av.z;
        As[aCol + 3][aRow] = av.w;
        *(float4*)&Bs[bRow][bCol] = bv;
        __syncthreads();
#pragma unroll
        for (int kk = 0; kk < BK; ++kk) {
            float a[TM], b[TN];
#pragma unroll
            for (int i = 0; i < TM; ++i) a[i] = As[kk][tr + i];
#pragma unroll
            for (int j = 0; j < TN; ++j) b[j] = Bs[kk][tc + j];
#pragma unroll
            for (int i = 0; i < TM; ++i)
#pragma unroll
                for (int j = 0; j < TN; ++j) acc[i][j] += a[i] * b[j];
        }
        __syncthreads();
    }
#pragma unroll
    for (int i = 0; i < TM; ++i) {
        int r = rowBase + tr + i;
        if (r >= M) break;
#pragma unroll
        for (int j = 0; j < TN; ++j) {
            int c = colBase + tc + j;
            if (c >= N) continue;
            C[(size_t)r * N + c] = acc[i][j];
        }
    }
}

// ---------------- GraphNorm ----------------
__global__ void k_stats(size_t x_off) {
    const float* x = g_buf + x_off;
    int col = threadIdx.x;
    float s = 0.f, q = 0.f;
    for (int i = blockIdx.x; i < NN; i += gridDim.x) {
        float v = x[(size_t)i * 512 + col];
        s += v;
        q += v * v;
    }
    atomicAdd(&g_stats[col], s);
    atomicAdd(&g_stats[512 + col], q);
}
__global__ void k_gnorm(size_t x_off, size_t out_off,
                        const float* __restrict__ w,
                        const float* __restrict__ b,
                        const float* __restrict__ a, int emit_bf16) {
    const float* x = g_buf + x_off;
    float* out = g_buf + out_off;
    int col = threadIdx.x;
    const float invn = 1.f / (float)NN;
    float m  = g_stats[col] * invn;
    float am = a[col] * m;
    float var = g_stats[512 + col] * invn - 2.f * am * m + am * am;
    float sc = rsqrtf(var + 1e-5f) * w[col];
    float sh = b[col];
    for (int i = blockIdx.x; i < NN; i += gridDim.x) {
        float v = (x[(size_t)i * 512 + col] - am) * sc + sh;
        out[(size_t)i * 512 + col] = v;
        if (emit_bf16) {
            __nv_bfloat16 h, l;
            split1(v, h, l);
            g_ah[(size_t)i * 512 + col] = h;
            g_al[(size_t)i * 512 + col] = l;
        }
    }
}

// W3 (4,512,16) -> W3t (512,64): [i][k*16+j]
__global__ void k_w3t(const float* __restrict__ W3) {
    int idx = blockIdx.x * blockDim.x + threadIdx.x;
    if (idx >= 4 * 512 * 16) return;
    int k = idx >> 13;
    int r = idx & 8191;
    int i = r >> 4, j = r & 15;
    g_buf[W3T_OFF + i * 64 + k * 16 + j] = W3[idx];
}

// ---------------- launcher ----------------
extern "C" void kernel_launch(void* const* d_in, const int* in_sizes, int n_in,
                              void* d_out, int out_size) {
    const float* x    = (const float*)d_in[0];
    const void*  ei   = d_in[1];
    const float* W1   = (const float*)d_in[2];
    const float* b1   = (const float*)d_in[3];
    const float* W2   = (const float*)d_in[4];
    const float* b2   = (const float*)d_in[5];
    const float* W3   = (const float*)d_in[6];
    const float* b3   = (const float*)d_in[7];
    const float* gn1w = (const float*)d_in[8];
    const float* gn1b = (const float*)d_in[9];
    const float* gn1a = (const float*)d_in[10];
    const float* gn2w = (const float*)d_in[11];
    const float* gn2b = (const float*)d_in[12];
    const float* gn2a = (const float*)d_in[13];
    float* out = (float*)d_out;

    cudaFuncSetAttribute(k_gemm_mma, cudaFuncAttributeMaxDynamicSharedMemorySize, GSM_TOTAL);

    // graph preprocessing
    k_detect<<<1, 256>>>((const int*)ei);
    k_zero_init<<<(NN + 255) / 256, 256>>>();
    k_deg<<<(EE + 255) / 256, 256>>>(ei);
    k_dinv<<<(NN + 255) / 256, 256>>>();
    k_scan<<<1, 1024>>>();
    k_scatter<<<(EE + 255) / 256, 256>>>(ei);

    // weight splits (independent of graph)
    k_wsplit<<<1024, 256>>>(W1, 0);
    k_wsplit<<<1024, 256>>>(W2, 1);
    k_wsplit<<<1024, 256>>>(W2 + 262144, 2);
    k_wsplit<<<1024, 256>>>(W2 + 524288, 3);
    k_wsplit<<<1024, 256>>>(W2 + 786432, 4);

    const size_t P0 = A_OFF;                       // [NN,128] fp32 ping
    const size_t P1 = A_OFF + (size_t)NN * 128;    // [NN,128] fp32 pong
    dim3 gg(4, (NN + 127) / 128);

    // ---- layer 1: width-128 props; bf16 concat cols fill g_ah/g_al ----
    k_xsplit<<<(NN * 32 + 255) / 256, 256>>>(x);
    k_prop<32><<<(NN + 7) / 8, 256>>>(x, 0, 32, P0, 32, nullptr, 0, 0, 0, nullptr, 128, 0);
    k_prop<32><<<(NN + 7) / 8, 256>>>(nullptr, P0, 32, P1, 32, nullptr, 0, 0, 0, nullptr, 256, 0);
    k_prop<32><<<(NN + 7) / 8, 256>>>(nullptr, P1, 32, P0, 32, nullptr, 0, 0, 0, nullptr, 384, 0);
    k_gemm_mma<<<gg, 256, GSM_TOTAL>>>(0, B_OFF, NN, b1, 1, 0);

    // graphnorm 1: B -> C fp32 h0 (+bf16)
    k_stats<<<512, 512>>>(B_OFF);
    k_gnorm<<<512, 512>>>(B_OFF, C_OFF, gn1w, gn1b, gn1a, 1);

    // ---- layer 2: ACC = sum_k h_k @ W2[k]; 512-wide props split in halves --
    const int PG = (NN + 3) / 4;  // G=64: 4 nodes/block
    k_gemm_mma<<<gg, 256, GSM_TOTAL>>>(1, B_OFF, NN, b2, 0, 0);
    k_prop<64><<<PG, 256>>>(nullptr, C_OFF, 128, A_OFF, 128, nullptr, 0, 0, 0, nullptr, 0, 0);
    k_prop<64><<<PG, 256>>>(nullptr, C_OFF, 128, A_OFF, 128, nullptr, 0, 0, 0, nullptr, 256, 64);
    k_gemm_mma<<<gg, 256, GSM_TOTAL>>>(2, B_OFF, NN, nullptr, 0, 1);
    k_prop<64><<<PG, 256>>>(nullptr, A_OFF, 128, C_OFF, 128, nullptr, 0, 0, 0, nullptr, 0, 0);
    k_prop<64><<<PG, 256>>>(nullptr, A_OFF, 128, C_OFF, 128, nullptr, 0, 0, 0, nullptr, 256, 64);
    k_gemm_mma<<<gg, 256, GSM_TOTAL>>>(3, B_OFF, NN, nullptr, 0, 1);
    k_prop<64><<<PG, 256>>>(nullptr, C_OFF, 128, A_OFF, 128, nullptr, 0, 0, 0, nullptr, 0, 0);
    k_prop<64><<<PG, 256>>>(nullptr, C_OFF, 128, A_OFF, 128, nullptr, 0, 0, 0, nullptr, 256, 64);
    k_gemm_mma<<<gg, 256, GSM_TOTAL>>>(4, B_OFF, NN, nullptr, 1, 1);

    // graphnorm 2: B -> C (H2, fp32 only)
    k_zero_stats<<<4, 256>>>();
    k_stats<<<512, 512>>>(B_OFF);
    k_gnorm<<<512, 512>>>(B_OFF, C_OFF, gn2w, gn2b, gn2a, 0);

    // ---- layer 3: Horner on 16-wide features (SIMT) ----
    k_w3t<<<(4 * 512 * 16 + 255) / 256, 256>>>(W3);
    dim3 g3(1, (NN + BM - 1) / BM);
    k_sgemm<<<g3, 256>>>(C_OFF, W3T_OFF, U_OFF, NN, 64, 512);
    k_prop<4><<<(NN + 63) / 64, 256>>>(nullptr, U_OFF + 48, 16, T1_OFF, 4, nullptr, U_OFF + 32, 16, 1, nullptr, -1, 0);
    k_prop<4><<<(NN + 63) / 64, 256>>>(nullptr, T1_OFF, 4, T2_OFF, 4, nullptr, U_OFF + 16, 16, 1, nullptr, -1, 0);
    k_prop<4><<<(NN + 63) / 64, 256>>>(nullptr, T2_OFF, 4, 0, 4, out, U_OFF, 16, 1, b3, -1, 0);
}

// round 11
// speedup vs baseline: 2.2567x; 1.1986x over previous
#include <cuda_runtime.h>
#include <cuda_bf16.h>
#include <cstdint>

// Problem constants (fixed by the reference)
#define NN   100000
#define EE   3200000

// ---------------- scratch (device globals: no allocation allowed) ----------
#define NS       ((size_t)51200000)       // NN*512 floats
#define A_OFF    ((size_t)0)              // fp32 ping (layer1 width128 / layer2 h1,h3)
#define B_OFF    (NS)                     // fp32 GEMM ACC / pre-norm H
#define C_OFF    (2*NS)                   // fp32 h0,h2 / H2
#define U_OFF    (3*NS)                   // NN*64
#define T1_OFF   (U_OFF + 6400000)        // NN*16
#define T2_OFF   (T1_OFF + 1600000)       // NN*16
#define BUF_TOTAL (T2_OFF + 1600000)

__device__ float g_buf[BUF_TOTAL];
__device__ float g_deg[NN];
__device__ float g_dinv[NN];
__device__ int   g_off[NN + 1];
__device__ int   g_cursor[NN];
__device__ int   g_src[EE];
__device__ float g_w[EE];
__device__ float g_stats[1024];
__device__ int   g_is64;
__device__ int   g_total;

// bf16 split buffers: A operand hi/lo [NN,512], weights hi/lo [5][2][512*512]
__device__ __nv_bfloat16 g_ah[(size_t)NN * 512];
__device__ __nv_bfloat16 g_al[(size_t)NN * 512];
__device__ __nv_bfloat16 g_wb[5 * 2 * 262144];
__device__ __nv_bfloat16 g_w3b[2 * 64 * 512];   // W3 transposed [64(N)][512(K)] hi/lo

// ---------------- PTX helpers (baseline ISA only — no 'a' features) --------
__device__ __forceinline__ uint32_t smem_u32(const void* p) {
    uint32_t a;
    asm("{ .reg .u64 t; cvta.to.shared.u64 t, %1; cvt.u32.u64 %0, t; }"
        : "=r"(a) : "l"(p));
    return a;
}

#define SWZ64(off) ((off) ^ (((off) >> 3) & 0x30))

#define LDSM4(r, addr) \
    asm volatile("ldmatrix.sync.aligned.m8n8.x4.shared.b16 {%0,%1,%2,%3}, [%4];" \
        : "=r"((r)[0]), "=r"((r)[1]), "=r"((r)[2]), "=r"((r)[3]) : "r"(addr))
#define LDSM2(r, addr) \
    asm volatile("ldmatrix.sync.aligned.m8n8.x2.shared.b16 {%0,%1}, [%2];" \
        : "=r"((r)[0]), "=r"((r)[1]) : "r"(addr))
#define MMA_BF16(d, a, b) \
    asm volatile("mma.sync.aligned.m16n8k16.row.col.f32.bf16.bf16.f32 " \
        "{%0,%1,%2,%3}, {%4,%5,%6,%7}, {%8,%9}, {%0,%1,%2,%3};" \
        : "+f"((d)[0]), "+f"((d)[1]), "+f"((d)[2]), "+f"((d)[3]) \
        : "r"((a)[0]), "r"((a)[1]), "r"((a)[2]), "r"((a)[3]), \
          "r"((b)[0]), "r"((b)[1]))
#define CP_ASYNC16(smaddr, gptr, sz) \
    asm volatile("cp.async.cg.shared.global [%0], [%1], 16, %2;" \
        :: "r"(smaddr), "l"(gptr), "r"(sz) : "memory")

// ---------------- bf16 split helpers ----------------
__device__ __forceinline__ void split1(float v, __nv_bfloat16& h, __nv_bfloat16& l) {
    h = __float2bfloat16(v);
    l = __float2bfloat16(v - __bfloat162float(h));
}
__device__ __forceinline__ void split4_store(float4 v, __nv_bfloat16* ph, __nv_bfloat16* pl) {
    union { __nv_bfloat16 b[4]; uint2 u; } H, L;
    split1(v.x, H.b[0], L.b[0]);
    split1(v.y, H.b[1], L.b[1]);
    split1(v.z, H.b[2], L.b[2]);
    split1(v.w, H.b[3], L.b[3]);
    *(uint2*)ph = H.u;
    *(uint2*)pl = L.u;
}

// ---------------- edge dtype detection ----------------
__global__ void k_detect(const int* __restrict__ ei32) {
    __shared__ int any;
    if (threadIdx.x == 0) any = 0;
    __syncthreads();
    for (int i = threadIdx.x; i < 8192; i += blockDim.x)
        if (ei32[2 * i + 1] != 0) any = 1;
    __syncthreads();
    if (threadIdx.x == 0) g_is64 = (any == 0) ? 1 : 0;
}
__device__ __forceinline__ int edge_val(const void* ei, size_t idx) {
    if (g_is64) return (int)((const long long*)ei)[idx];
    return ((const int*)ei)[idx];
}

// ---------------- graph preprocessing ----------------
__global__ void k_zero_init() {
    int i = blockIdx.x * blockDim.x + threadIdx.x;
    if (i < NN) { g_deg[i] = 0.f; g_cursor[i] = 0; }
    if (i < 1024) g_stats[i] = 0.f;
    if (i == 0) g_total = 0;
}
__global__ void k_zero_stats() {
    int i = blockIdx.x * blockDim.x + threadIdx.x;
    if (i < 1024) g_stats[i] = 0.f;
}
__global__ void k_deg(const void* __restrict__ ei) {
    int e = blockIdx.x * blockDim.x + threadIdx.x;
    if (e >= EE) return;
    atomicAdd(&g_deg[edge_val(ei, (size_t)EE + e)], 1.f);
}
__global__ void k_dinv() {
    int i = blockIdx.x * blockDim.x + threadIdx.x;
    if (i >= NN) return;
    float d = g_deg[i];
    g_dinv[i] = d > 0.f ? rsqrtf(d) : 0.f;
}
// CSR range allocation: warp-scan of degrees + 1 atomic per warp.
// Node ranges are contiguous but in arbitrary order — valid CSR.
__global__ void k_alloc() {
    int i = blockIdx.x * blockDim.x + threadIdx.x;
    int lane = threadIdx.x & 31;
    int d = (i < NN) ? (int)g_deg[i] : 0;
    int sum = d;
#pragma unroll
    for (int o = 1; o < 32; o <<= 1) {
        int t = __shfl_up_sync(0xFFFFFFFFu, sum, o);
        if (lane >= o) sum += t;
    }
    int excl = sum - d;
    int wtot = __shfl_sync(0xFFFFFFFFu, sum, 31);
    int base = 0;
    if (lane == 0) base = atomicAdd(&g_total, wtot);
    base = __shfl_sync(0xFFFFFFFFu, base, 0);
    if (i < NN) g_off[i] = base + excl;
}
__global__ void k_scatter(const void* __restrict__ ei) {
    int e = blockIdx.x * blockDim.x + threadIdx.x;
    if (e >= EE) return;
    int r = edge_val(ei, (size_t)e);
    int c = edge_val(ei, (size_t)EE + e);
    int pos = g_off[c] + atomicAdd(&g_cursor[c], 1);
    g_src[pos] = r;
    g_w[pos] = g_dinv[r] * g_dinv[c];
}

// x (fp32 [NN,128]) -> bf16 hi/lo into cols 0..127 of g_ah/g_al
__global__ void k_xsplit(const float* __restrict__ x) {
    int idx = blockIdx.x * blockDim.x + threadIdx.x;
    if (idx >= NN * 32) return;
    int m = idx >> 5, c = (idx & 31) * 4;
    float4 v = ((const float4*)x)[idx];
    split4_store(v, &g_ah[(size_t)m * 512 + c], &g_al[(size_t)m * 512 + c]);
}

// weight transpose+split: W [512(K)][512(N)] fp32 -> g_wb[wsel] as [N][K] bf16 hi/lo
__global__ void k_wsplit(const float* __restrict__ W, int wsel) {
    int idx = blockIdx.x * blockDim.x + threadIdx.x;
    if (idx >= 262144) return;
    int n = idx >> 9, k = idx & 511;
    float v = W[(size_t)k * 512 + n];
    __nv_bfloat16 h, l;
    split1(v, h, l);
    g_wb[(size_t)wsel * 524288 + (size_t)n * 512 + k] = h;
    g_wb[(size_t)wsel * 524288 + 262144 + (size_t)n * 512 + k] = l;
}

// W3 (4,512,16) -> g_w3b [n=k*16+j][i] bf16 hi/lo
__global__ void k_w3split(const float* __restrict__ W3) {
    int idx = blockIdx.x * blockDim.x + threadIdx.x;
    if (idx >= 32768) return;
    int k = idx >> 13;
    int r = idx & 8191;
    int i = r >> 4, j = r & 15;
    int n = k * 16 + j;
    __nv_bfloat16 h, l;
    split1(W3[idx], h, l);
    g_w3b[n * 512 + i] = h;
    g_w3b[32768 + n * 512 + i] = l;
}

// ---------------- CSR gather propagation (+ optional bf16 hi/lo emit) -------
// G threads/node, 4 cols per thread. cbase4 = column offset in float4 units.
template <int G>
__global__ void k_prop(const float* __restrict__ in_ext, size_t in_off, int in_s4,
                       size_t out_off, int out_s4, float* out_ext,
                       size_t add_off, int add_s4, int has_add,
                       const float* __restrict__ bias, int bcol, int cbase4) {
    const int per = 256 / G;
    int node = blockIdx.x * per + (int)(threadIdx.x / G);
    int lane = threadIdx.x % G;
    if (node >= NN) return;
    int s = g_off[node];
    int e = s + (int)__ldg(&g_deg[node]);
    const float4* in4 = in_ext ? (const float4*)in_ext : (const float4*)(g_buf + in_off);
    float4 acc = make_float4(0.f, 0.f, 0.f, 0.f);
    int p = s;
    for (; p + 1 < e; p += 2) {
        int   j0 = __ldg(&g_src[p]),     j1 = __ldg(&g_src[p + 1]);
        float w0 = __ldg(&g_w[p]),       w1 = __ldg(&g_w[p + 1]);
        float4 v0 = __ldg(&in4[(size_t)j0 * in_s4 + cbase4 + lane]);
        float4 v1 = __ldg(&in4[(size_t)j1 * in_s4 + cbase4 + lane]);
        acc.x += w0 * v0.x + w1 * v1.x;
        acc.y += w0 * v0.y + w1 * v1.y;
        acc.z += w0 * v0.z + w1 * v1.z;
        acc.w += w0 * v0.w + w1 * v1.w;
    }
    if (p < e) {
        int   j  = __ldg(&g_src[p]);
        float wt = __ldg(&g_w[p]);
        float4 v = __ldg(&in4[(size_t)j * in_s4 + cbase4 + lane]);
        acc.x += wt * v.x; acc.y += wt * v.y;
        acc.z += wt * v.z; acc.w += wt * v.w;
    }
    if (has_add) {
        float4 a = ((const float4*)(g_buf + add_off))[(size_t)node * add_s4 + cbase4 + lane];
        acc.x += a.x; acc.y += a.y; acc.z += a.z; acc.w += a.w;
    }
    if (bias) {
        float4 b = ((const float4*)bias)[cbase4 + lane];
        acc.x += b.x; acc.y += b.y; acc.z += b.z; acc.w += b.w;
    }
    float4* out4 = out_ext ? (float4*)out_ext : (float4*)(g_buf + out_off);
    out4[(size_t)node * out_s4 + cbase4 + lane] = acc;
    if (bcol >= 0) {
        size_t bo = (size_t)node * 512 + bcol + lane * 4;
        split4_store(acc, &g_ah[bo], &g_al[bo]);
    }
}

// ---------------- bf16x3 mma.sync GEMM, cp.async 2-stage pipeline ----------
// C[M,512], CTA tile 128x128, K=512 in 16 chunks of 32.
// Stage = 4 matrices x (128 rows x 64B, SW64 swizzle) = 32KB; 2 stages = 64KB.
#define GSM_TOTAL 65536

__global__ __launch_bounds__(256, 2)
void k_gemm_mma(int wsel, size_t c_off, int M,
                const float* __restrict__ bias, int relu, int accum) {
    extern __shared__ char smem[];
    uint32_t sb = smem_u32(smem);
    int tid = threadIdx.x, wid = tid >> 5, lane = tid & 31;
    int rowBase = blockIdx.y * 128, colBase = blockIdx.x * 128;
    int warpM = (wid & 1) * 64, warpN = (wid >> 1) * 32;
    const __nv_bfloat16* Bhi = g_wb + (size_t)wsel * 524288;
    const __nv_bfloat16* Blo = Bhi + 262144;

    float acc[4][4][4];
#pragma unroll
    for (int mi = 0; mi < 4; ++mi)
#pragma unroll
        for (int ni = 0; ni < 4; ++ni)
#pragma unroll
            for (int q = 0; q < 4; ++q) acc[mi][ni][q] = 0.f;

    auto load_stage = [&](int c, int st) {
#pragma unroll
        for (int i = 0; i < 8; ++i) {
            int it = tid + i * 256;           // 0..2047
            int mat = it >> 9;                // 0 AH, 1 AL, 2 BH, 3 BL
            int idx = it & 511;
            int r = idx >> 2, u = idx & 3;    // row 0..127, 16B unit 0..3
            uint32_t so = sb + (uint32_t)st * 32768 + (uint32_t)mat * 8192 +
                          SWZ64((uint32_t)(r * 64 + u * 16));
            const __nv_bfloat16* src;
            int gr, sz = 16;
            if (mat == 0)      { src = g_ah; gr = rowBase + r; if (gr >= M) { gr = 0; sz = 0; } }
            else if (mat == 1) { src = g_al; gr = rowBase + r; if (gr >= M) { gr = 0; sz = 0; } }
            else if (mat == 2) { src = Bhi;  gr = colBase + r; }
            else               { src = Blo;  gr = colBase + r; }
            const void* gp = src + (size_t)gr * 512 + c * 32 + u * 8;
            CP_ASYNC16(so, gp, sz);
        }
        asm volatile("cp.async.commit_group;" ::: "memory");
    };

    load_stage(0, 0);
    for (int c = 0; c < 16; ++c) {
        if (c + 1 < 16) {
            load_stage(c + 1, (c + 1) & 1);
            asm volatile("cp.async.wait_group 1;" ::: "memory");
        } else {
            asm volatile("cp.async.wait_group 0;" ::: "memory");
        }
        __syncthreads();
        uint32_t sbase = sb + (uint32_t)(c & 1) * 32768;
#pragma unroll
        for (int ks = 0; ks < 2; ++ks) {
            uint32_t bH[4][2], bL[4][2];
            int bl = lane & 15;
            int brow0 = warpN + (bl & 7);
            uint32_t bunit = ks * 2 + ((bl >> 3) & 1);
#pragma unroll
            for (int ni = 0; ni < 4; ++ni) {
                uint32_t off = SWZ64((uint32_t)((brow0 + ni * 8) * 64 + bunit * 16));
                LDSM2(bH[ni], sbase + 16384 + off);
                LDSM2(bL[ni], sbase + 24576 + off);
            }
            int arow = warpM + (lane & 15);
            uint32_t aunit = ks * 2 + (lane >> 4);
#pragma unroll
            for (int mi = 0; mi < 4; ++mi) {
                uint32_t aH[4], aL[4];
                uint32_t off = SWZ64((uint32_t)((arow + mi * 16) * 64 + aunit * 16));
                LDSM4(aH, sbase + off);
                LDSM4(aL, sbase + 8192 + off);
#pragma unroll
                for (int ni = 0; ni < 4; ++ni) {
                    MMA_BF16(acc[mi][ni], aH, bH[ni]);
                    MMA_BF16(acc[mi][ni], aH, bL[ni]);
                    MMA_BF16(acc[mi][ni], aL, bH[ni]);
                }
            }
        }
        __syncthreads();
    }

    // epilogue: c frag thread t -> rows (t>>2), (t>>2)+8; cols 2*(t&3), +1
    float* C = g_buf + c_off;
#pragma unroll
    for (int mi = 0; mi < 4; ++mi) {
        int r0 = rowBase + warpM + mi * 16 + (lane >> 2);
#pragma unroll
        for (int ni = 0; ni < 4; ++ni) {
            int cc = colBase + warpN + ni * 8 + (lane & 3) * 2;
            float2 v0 = make_float2(acc[mi][ni][0], acc[mi][ni][1]);
            float2 v1 = make_float2(acc[mi][ni][2], acc[mi][ni][3]);
            if (bias) {
                float2 bb = *(const float2*)&bias[cc];
                v0.x += bb.x; v0.y += bb.y;
                v1.x += bb.x; v1.y += bb.y;
            }
            if (r0 < M) {
                float* p = C + (size_t)r0 * 512 + cc;
                if (accum) { float2 o = *(float2*)p; v0.x += o.x; v0.y += o.y; }
                if (relu) { v0.x = fmaxf(v0.x, 0.f); v0.y = fmaxf(v0.y, 0.f); }
                *(float2*)p = v0;
            }
            if (r0 + 8 < M) {
                float* p = C + (size_t)(r0 + 8) * 512 + cc;
                if (accum) { float2 o = *(float2*)p; v1.x += o.x; v1.y += o.y; }
                if (relu) { v1.x = fmaxf(v1.x, 0.f); v1.y = fmaxf(v1.y, 0.f); }
                *(float2*)p = v1;
            }
        }
    }
}

// ---------------- bf16x3 mma.sync GEMM, 128x64 tile (layer 3: U = H2@W3t) --
// A = g_ah/g_al (H2 bf16), B = g_w3b [64][512]. C = g_buf[U_OFF] (stride 64).
// Stage: AH 8K | AL 8K | BH 4K | BL 4K = 24KB; 2 stages = 48KB.
#define GSM64_TOTAL 49152

__global__ __launch_bounds__(256, 2)
void k_gemm_mma64(int M) {
    extern __shared__ char smem[];
    uint32_t sb = smem_u32(smem);
    int tid = threadIdx.x, wid = tid >> 5, lane = tid & 31;
    int rowBase = blockIdx.x * 128;
    int warpM = (wid & 3) * 32, warpN = (wid >> 2) * 32;

    float acc[2][4][4];
#pragma unroll
    for (int mi = 0; mi < 2; ++mi)
#pragma unroll
        for (int ni = 0; ni < 4; ++ni)
#pragma unroll
            for (int q = 0; q < 4; ++q) acc[mi][ni][q] = 0.f;

    auto load_stage = [&](int c, int st) {
#pragma unroll
        for (int i = 0; i < 6; ++i) {
            int it = tid + i * 256;    // 0..1535
            uint32_t so;
            const void* gp;
            int sz = 16;
            if (it < 1024) {           // A: hi/lo, 128 rows x 4 units
                int hl = it >> 9, idx = it & 511;
                int r = idx >> 2, u = idx & 3;
                so = sb + (uint32_t)st * 24576 + (uint32_t)hl * 8192 +
                     SWZ64((uint32_t)(r * 64 + u * 16));
                int gr = rowBase + r;
                if (gr >= M) { gr = 0; sz = 0; }
                const __nv_bfloat16* src = hl ? g_al : g_ah;
                gp = src + (size_t)gr * 512 + c * 32 + u * 8;
            } else {                   // B: hi/lo, 64 rows x 4 units
                int itb = it - 1024;
                int hl = itb >> 8, idx = itb & 255;
                int r = idx >> 2, u = idx & 3;
                so = sb + (uint32_t)st * 24576 + 16384 + (uint32_t)hl * 4096 +
                     SWZ64((uint32_t)(r * 64 + u * 16));
                gp = g_w3b + (size_t)hl * 32768 + (size_t)r * 512 + c * 32 + u * 8;
            }
            CP_ASYNC16(so, gp, sz);
        }
        asm volatile("cp.async.commit_group;" ::: "memory");
    };

    load_stage(0, 0);
    for (int c = 0; c < 16; ++c) {
        if (c + 1 < 16) {
            load_stage(c + 1, (c + 1) & 1);
            asm volatile("cp.async.wait_group 1;" ::: "memory");
        } else {
            asm volatile("cp.async.wait_group 0;" ::: "memory");
        }
        __syncthreads();
        uint32_t sbase = sb + (uint32_t)(c & 1) * 24576;
#pragma unroll
        for (int ks = 0; ks < 2; ++ks) {
            uint32_t bH[4][2], bL[4][2];
            int bl = lane & 15;
            int brow0 = warpN + (bl & 7);
            uint32_t bunit = ks * 2 + ((bl >> 3) & 1);
#pragma unroll
            for (int ni = 0; ni < 4; ++ni) {
                uint32_t off = SWZ64((uint32_t)((brow0 + ni * 8) * 64 + bunit * 16));
                LDSM2(bH[ni], sbase + 16384 + off);
                LDSM2(bL[ni], sbase + 20480 + off);
            }
            int arow = warpM + (lane & 15);
            uint32_t aunit = ks * 2 + (lane >> 4);
#pragma unroll
            for (int mi = 0; mi < 2; ++mi) {
                uint32_t aH[4], aL[4];
                uint32_t off = SWZ64((uint32_t)((arow + mi * 16) * 64 + aunit * 16));
                LDSM4(aH, sbase + off);
                LDSM4(aL, sbase + 8192 + off);
#pragma unroll
                for (int ni = 0; ni < 4; ++ni) {
                    MMA_BF16(acc[mi][ni], aH, bH[ni]);
                    MMA_BF16(acc[mi][ni], aH, bL[ni]);
                    MMA_BF16(acc[mi][ni], aL, bH[ni]);
                }
            }
        }
        __syncthreads();
    }

    float* C = g_buf + U_OFF;
#pragma unroll
    for (int mi = 0; mi < 2; ++mi) {
        int r0 = rowBase + warpM + mi * 16 + (lane >> 2);
#pragma unroll
        for (int ni = 0; ni < 4; ++ni) {
            int cc = warpN + ni * 8 + (lane & 3) * 2;
            if (r0 < M)
                *(float2*)(C + (size_t)r0 * 64 + cc) =
                    make_float2(acc[mi][ni][0], acc[mi][ni][1]);
            if (r0 + 8 < M)
                *(float2*)(C + (size_t)(r0 + 8) * 64 + cc) =
                    make_float2(acc[mi][ni][2], acc[mi][ni][3]);
        }
    }
}

// ---------------- GraphNorm ----------------
__global__ void k_stats(size_t x_off) {
    const float* x = g_buf + x_off;
    int col = threadIdx.x;
    float s = 0.f, q = 0.f;
    for (int i = blockIdx.x; i < NN; i += gridDim.x) {
        float v = x[(size_t)i * 512 + col];
        s += v;
        q += v * v;
    }
    atomicAdd(&g_stats[col], s);
    atomicAdd(&g_stats[512 + col], q);
}
__global__ void k_gnorm(size_t x_off, size_t out_off,
                        const float* __restrict__ w,
                        const float* __restrict__ b,
                        const float* __restrict__ a, int emit_bf16) {
    const float* x = g_buf + x_off;
    float* out = g_buf + out_off;
    int col = threadIdx.x;
    const float invn = 1.f / (float)NN;
    float m  = g_stats[col] * invn;
    float am = a[col] * m;
    float var = g_stats[512 + col] * invn - 2.f * am * m + am * am;
    float sc = rsqrtf(var + 1e-5f) * w[col];
    float sh = b[col];
    for (int i = blockIdx.x; i < NN; i += gridDim.x) {
        float v = (x[(size_t)i * 512 + col] - am) * sc + sh;
        out[(size_t)i * 512 + col] = v;
        if (emit_bf16) {
            __nv_bfloat16 h, l;
            split1(v, h, l);
            g_ah[(size_t)i * 512 + col] = h;
            g_al[(size_t)i * 512 + col] = l;
        }
    }
}

// ---------------- launcher ----------------
extern "C" void kernel_launch(void* const* d_in, const int* in_sizes, int n_in,
                              void* d_out, int out_size) {
    const float* x    = (const float*)d_in[0];
    const void*  ei   = d_in[1];
    const float* W1   = (const float*)d_in[2];
    const float* b1   = (const float*)d_in[3];
    const float* W2   = (const float*)d_in[4];
    const float* b2   = (const float*)d_in[5];
    const float* W3   = (const float*)d_in[6];
    const float* b3   = (const float*)d_in[7];
    const float* gn1w = (const float*)d_in[8];
    const float* gn1b = (const float*)d_in[9];
    const float* gn1a = (const float*)d_in[10];
    const float* gn2w = (const float*)d_in[11];
    const float* gn2b = (const float*)d_in[12];
    const float* gn2a = (const float*)d_in[13];
    float* out = (float*)d_out;

    cudaFuncSetAttribute(k_gemm_mma, cudaFuncAttributeMaxDynamicSharedMemorySize, GSM_TOTAL);
    cudaFuncSetAttribute(k_gemm_mma64, cudaFuncAttributeMaxDynamicSharedMemorySize, GSM64_TOTAL);

    // graph preprocessing
    k_detect<<<1, 256>>>((const int*)ei);
    k_zero_init<<<(NN + 255) / 256, 256>>>();
    k_deg<<<(EE + 255) / 256, 256>>>(ei);
    k_dinv<<<(NN + 255) / 256, 256>>>();
    k_alloc<<<(NN + 255) / 256, 256>>>();
    k_scatter<<<(EE + 255) / 256, 256>>>(ei);

    // weight splits (independent of graph)
    k_wsplit<<<1024, 256>>>(W1, 0);
    k_wsplit<<<1024, 256>>>(W2, 1);
    k_wsplit<<<1024, 256>>>(W2 + 262144, 2);
    k_wsplit<<<1024, 256>>>(W2 + 524288, 3);
    k_wsplit<<<1024, 256>>>(W2 + 786432, 4);
    k_w3split<<<128, 256>>>(W3);

    const size_t P0 = A_OFF;                       // [NN,128] fp32 ping
    const size_t P1 = A_OFF + (size_t)NN * 128;    // [NN,128] fp32 pong
    dim3 gg(4, (NN + 127) / 128);

    // ---- layer 1: width-128 props; bf16 concat cols fill g_ah/g_al ----
    k_xsplit<<<(NN * 32 + 255) / 256, 256>>>(x);
    k_prop<32><<<(NN + 7) / 8, 256>>>(x, 0, 32, P0, 32, nullptr, 0, 0, 0, nullptr, 128, 0);
    k_prop<32><<<(NN + 7) / 8, 256>>>(nullptr, P0, 32, P1, 32, nullptr, 0, 0, 0, nullptr, 256, 0);
    k_prop<32><<<(NN + 7) / 8, 256>>>(nullptr, P1, 32, P0, 32, nullptr, 0, 0, 0, nullptr, 384, 0);
    k_gemm_mma<<<gg, 256, GSM_TOTAL>>>(0, B_OFF, NN, b1, 1, 0);

    // graphnorm 1: B -> C fp32 h0 (+bf16)
    k_stats<<<512, 512>>>(B_OFF);
    k_gnorm<<<512, 512>>>(B_OFF, C_OFF, gn1w, gn1b, gn1a, 1);

    // ---- layer 2: ACC = sum_k h_k @ W2[k]; props in 4 L2-resident quarters -
    const int PQ = (NN + 7) / 8;  // G=32: 8 nodes/block
    k_gemm_mma<<<gg, 256, GSM_TOTAL>>>(1, B_OFF, NN, b2, 0, 0);
    k_prop<32><<<PQ, 256>>>(nullptr, C_OFF, 128, A_OFF, 128, nullptr, 0, 0, 0, nullptr, 0, 0);
    k_prop<32><<<PQ, 256>>>(nullptr, C_OFF, 128, A_OFF, 128, nullptr, 0, 0, 0, nullptr, 128, 32);
    k_prop<32><<<PQ, 256>>>(nullptr, C_OFF, 128, A_OFF, 128, nullptr, 0, 0, 0, nullptr, 256, 64);
    k_prop<32><<<PQ, 256>>>(nullptr, C_OFF, 128, A_OFF, 128, nullptr, 0, 0, 0, nullptr, 384, 96);
    k_gemm_mma<<<gg, 256, GSM_TOTAL>>>(2, B_OFF, NN, nullptr, 0, 1);
    k_prop<32><<<PQ, 256>>>(nullptr, A_OFF, 128, C_OFF, 128, nullptr, 0, 0, 0, nullptr, 0, 0);
    k_prop<32><<<PQ, 256>>>(nullptr, A_OFF, 128, C_OFF, 128, nullptr, 0, 0, 0, nullptr, 128, 32);
    k_prop<32><<<PQ, 256>>>(nullptr, A_OFF, 128, C_OFF, 128, nullptr, 0, 0, 0, nullptr, 256, 64);
    k_prop<32><<<PQ, 256>>>(nullptr, A_OFF, 128, C_OFF, 128, nullptr, 0, 0, 0, nullptr, 384, 96);
    k_gemm_mma<<<gg, 256, GSM_TOTAL>>>(3, B_OFF, NN, nullptr, 0, 1);
    k_prop<32><<<PQ, 256>>>(nullptr, C_OFF, 128, A_OFF, 128, nullptr, 0, 0, 0, nullptr, 0, 0);
    k_prop<32><<<PQ, 256>>>(nullptr, C_OFF, 128, A_OFF, 128, nullptr, 0, 0, 0, nullptr, 128, 32);
    k_prop<32><<<PQ, 256>>>(nullptr, C_OFF, 128, A_OFF, 128, nullptr, 0, 0, 0, nullptr, 256, 64);
    k_prop<32><<<PQ, 256>>>(nullptr, C_OFF, 128, A_OFF, 128, nullptr, 0, 0, 0, nullptr, 384, 96);
    k_gemm_mma<<<gg, 256, GSM_TOTAL>>>(4, B_OFF, NN, nullptr, 1, 1);

    // graphnorm 2: B -> C (H2 fp32 + bf16 for layer-3 mma)
    k_zero_stats<<<4, 256>>>();
    k_stats<<<512, 512>>>(B_OFF);
    k_gnorm<<<512, 512>>>(B_OFF, C_OFF, gn2w, gn2b, gn2a, 1);

    // ---- layer 3: U = H2 @ W3t (mma), then Horner on 16-wide features ----
    k_gemm_mma64<<<(NN + 127) / 128, 256, GSM64_TOTAL>>>(NN);
    k_prop<4><<<(NN + 63) / 64, 256>>>(nullptr, U_OFF + 48, 16, T1_OFF, 4, nullptr, U_OFF + 32, 16, 1, nullptr, -1, 0);
    k_prop<4><<<(NN + 63) / 64, 256>>>(nullptr, T1_OFF, 4, T2_OFF, 4, nullptr, U_OFF + 16, 16, 1, nullptr, -1, 0);
    k_prop<4><<<(NN + 63) / 64, 256>>>(nullptr, T2_OFF, 4, 0, 4, out, U_OFF, 16, 1, b3, -1, 0);
}